// round 6
// baseline (speedup 1.0000x reference)
#include <cuda_runtime.h>
#include <cuda_bf16.h>

#define BB 4
#define CC 32
#define PP 65536
#define KK 256
#define PCH 1024
#define CHUNKS 2
#define CTAS_PER_BATCH 32
#define GRID (BB * CTAS_PER_BATCH)   // 128
#define THREADS 512
#define FS 34                        // floats per pixel row; even (LDS.64-friendly), 2 mod 32

// smem: F_sh[PCH*FS] | A_sh[9*PCH] | plist[PCH] | cnt[KK] | offs[KK+1]
#define SMEM_FLOATS (PCH * FS + 9 * PCH + PCH + KK + KK + 1)
#define SMEM_BYTES (SMEM_FLOATS * 4)

// [b][k][c<32]=fsum, [b][k][32]=wsum. Zero at module load; last CTA re-zeroes -> replay-safe.
__device__ float g_fsum[BB * KK * (CC + 1)];
__device__ unsigned g_done;   // zero-init; last CTA resets

__global__ __launch_bounds__(THREADS, 1)
void spix_main(const float* __restrict__ feats,
               const float* __restrict__ assoc,
               const int*   __restrict__ idxmap,
               float* __restrict__ out) {
    extern __shared__ float sm[];
    float* F_sh  = sm;                        // [PCH][FS] pixel-major
    float* A_sh  = sm + PCH * FS;             // [9][PCH]
    int*   plist = (int*)(A_sh + 9 * PCH);    // [PCH] packed ((15-ix)<<12)|(pl<<2), sorted by bin
    int*   cnt   = plist + PCH;               // [KK]
    int*   offs  = cnt + KK;                  // [KK+1]

    const int b    = blockIdx.x >> 5;
    const int s    = blockIdx.x & 31;
    const int tid  = threadIdx.x;
    const int wid  = tid >> 5;
    const int lane = tid & 31;
    const int grp  = lane >> 4;               // half-warp: entry parity
    const int cl   = lane & 15;               // channel pair (2cl, 2cl+1)

    if (tid < KK) cnt[tid] = 0;
    __syncthreads();

    for (int ch = 0; ch < CHUNKS; ch++) {
        const int p0 = (s * CHUNKS + ch) * PCH;

        // ---- stage F, transpose to pixel-major via float2 (coalesced LDG, 2-way STS) ----
        {
            const int c   = tid >> 4;
            const int t16 = tid & 15;
            const float* src = feats + ((size_t)(b * CC + c)) * PP + p0 + 2 * t16;
            float* dstc = F_sh + c;
#pragma unroll 8
            for (int q = 0; q < 32; q++) {
                float2 v = *(const float2*)(src + 32 * q);
                const int p = 2 * t16 + 32 * q;
                dstc[(size_t)p * FS]       = v.x;
                dstc[(size_t)(p + 1) * FS] = v.y;
            }
        }
        // ---- stage A row-major [j][p] (coalesced float4, conflict-free) ----
        {
            const float* srcA = assoc + (size_t)b * 9 * PP;
            for (int t = tid; t < 9 * PCH / 4; t += THREADS) {
                const int j  = t >> 8;
                const int q4 = (t & 255) << 2;
                float4 v = *(const float4*)(srcA + (size_t)j * PP + p0 + q4);
                *(float4*)(A_sh + j * PCH + q4) = v;
            }
        }

        // ---- count pixels per base bin (2 px/thread; ~2K cheap shared atomics) ----
        const int idxA = idxmap[(size_t)b * PP + p0 + tid];
        const int idxB = idxmap[(size_t)b * PP + p0 + 512 + tid];
        atomicAdd(&cnt[idxA], 1);
        atomicAdd(&cnt[idxB], 1);
        __syncthreads();

        // ---- exclusive scan of 256 counts (warp 0) ----
        if (wid == 0) {
            int running = 0;
            for (int g = 0; g < KK / 32; g++) {
                const int v = cnt[g * 32 + lane];
                int incl = v;
#pragma unroll
                for (int d = 1; d < 32; d <<= 1) {
                    int n = __shfl_up_sync(0xffffffffu, incl, d);
                    if (lane >= d) incl += n;
                }
                offs[g * 32 + lane] = running + incl - v;
                running += __shfl_sync(0xffffffffu, incl, 31);
            }
            if (lane == 0) offs[KK] = PCH;
        }
        __syncthreads();
        if (tid < KK) cnt[tid] = offs[tid];    // cursors
        __syncthreads();

        // ---- place packed pixel records sorted by base bin (mirrored ix packing) ----
        plist[atomicAdd(&cnt[idxA], 1)] = ((15 - (idxA & 15)) << 12) | (tid << 2);
        plist[atomicAdd(&cnt[idxB], 1)] = ((15 - (idxB & 15)) << 12) | ((512 + tid) << 2);
        __syncthreads();
        if (tid < KK) cnt[tid] = 0;            // for next chunk; gather never reads cnt

        // ---- gather: warp = target row ky=wid; 3 contiguous runs per target bin ----
        const char* Fb = (const char*)F_sh + 8 * cl;
        const char* Ab = (const char*)A_sh;
        const int ky = wid;
        for (int kx = 0; kx < 16; kx++) {
            float a0 = 0.f, a1 = 0.f, aw = 0.f;
#pragma unroll
            for (int dy = -1; dy <= 1; dy++) {
                const int sy = ky + dy;
                if (sy < 0 || sy > 15) continue;
                const int xlo = kx > 0  ? kx - 1 : 0;
                const int xhi = kx < 15 ? kx + 1 : 15;
                const int beg = offs[sy * 16 + xlo];
                const int end = offs[sy * 16 + xhi + 1];
                // weight plane j = 3*(ky-sy+1) + (kx-ix+1) = 3*(1-dy) + (kx-ix+1)
                // pk = ((15-ix)<<12)|(pl<<2)  =>  waddr = Ab + ((3*(1-dy)+kx-14)<<12) + pk
                const char* A0k = Ab + ((3 * (1 - dy) + kx - 14) << 12);
                for (int e = beg; e < end; e += 2) {
                    const int  eg = e + grp;
                    const bool vv = eg < end;
                    const int  pk = plist[vv ? eg : e];        // always a valid run entry
                    float w = *(const float*)(A0k + pk);       // in-bounds even when !vv
                    if (!vv) w = 0.f;
                    const int pl4 = pk & 0xFFC;                // pl*4 (bits 2..11 only)
                    const float2 f = *(const float2*)(Fb + pl4 * FS);  // 136*pl + 8*cl
                    a0 += w * f.x;
                    a1 += w * f.y;
                    aw += w;
                }
            }
            a0 += __shfl_xor_sync(0xffffffffu, a0, 16);
            a1 += __shfl_xor_sync(0xffffffffu, a1, 16);
            aw += __shfl_xor_sync(0xffffffffu, aw, 16);
            float* gb = &g_fsum[(size_t)(b * KK + ky * 16 + kx) * (CC + 1)];
            if (lane < 16) {                    // fire-and-forget REDG
                atomicAdd(gb + 2 * cl,     a0);
                atomicAdd(gb + 2 * cl + 1, a1);
            } else if (lane == 16) {
                atomicAdd(gb + CC, aw);
            }
        }
        __syncthreads();
    }

    // ---- fused epilogue: last CTA normalizes, writes out, re-zeroes scratch ----
    __shared__ unsigned s_rank;
    __threadfence();                 // make this CTA's REDGs visible before signaling
    __syncthreads();
    if (tid == 0) s_rank = atomicAdd(&g_done, 1u);
    __syncthreads();
    if (s_rank == GRID - 1) {
        __threadfence();             // acquire: all other CTAs' REDGs visible
        for (int i = tid; i < BB * KK * CC; i += THREADS) {
            const int c  = i & 31;
            const int bk = i >> 5;
            const float ws = g_fsum[(size_t)bk * (CC + 1) + CC];
            const float fs = g_fsum[(size_t)bk * (CC + 1) + c];
            const int k = bk & 255, bb = bk >> 8;
            out[((size_t)(bb * CC) + c) * KK + k] = (ws > 1e-16f) ? fs / ws : 0.f;
        }
        __syncthreads();
        for (int i = tid; i < BB * KK * (CC + 1); i += THREADS) g_fsum[i] = 0.f;
        if (tid == 0) g_done = 0;
    }
}

extern "C" void kernel_launch(void* const* d_in, const int* in_sizes, int n_in,
                              void* d_out, int out_size) {
    const float* feats  = (const float*)d_in[0];
    const float* assoc  = (const float*)d_in[1];
    const int*   idxmap = (const int*)d_in[2];

    static int configured = 0;
    if (!configured) {
        cudaFuncSetAttribute(spix_main, cudaFuncAttributeMaxDynamicSharedMemorySize,
                             SMEM_BYTES);
        configured = 1;
    }
    spix_main<<<GRID, THREADS, SMEM_BYTES>>>(feats, assoc, idxmap, (float*)d_out);
}